// round 2
// baseline (speedup 1.0000x reference)
#include <cuda_runtime.h>
#include <math.h>

#define NN 100000   // nodes
#define NE 500000   // edges per head
#define NA 4        // angle heads
#define DD 128      // bond/hidden dim

// Scratch (allocation-guard-safe __device__ globals)
__device__ float g_P1[(size_t)NA * NN * DD];   // dst-side projection + bias
__device__ float g_P2[(size_t)NA * NN * DD];   // src-side projection
__device__ int   g_is64;                       // edge_index dtype flag

// ---------------------------------------------------------------------------
// Detect whether edge_index is stored as int64 or int32.
// Valid int64 indices are < NN; int32 pairs read as u64 are ~2^32-scale.
// ---------------------------------------------------------------------------
__global__ void detect_kernel(const unsigned long long* __restrict__ ei) {
    int ok = 1;
    for (int i = 0; i < 128; i++) {
        if (ei[i] >= (unsigned long long)NN) { ok = 0; break; }
    }
    g_is64 = ok;
}

// ---------------------------------------------------------------------------
// Projection: P[a][n][:] = bond[n] @ W[a][half*128 : +128][:] (+ b[a] if half==0)
// Grid: x = node tile (128 rows), y = head*2 + half. 256 threads, 8x8 micro.
// ---------------------------------------------------------------------------
__global__ void proj_kernel(const float* __restrict__ bond,
                            const float* __restrict__ W,
                            const float* __restrict__ bias) {
    const int head = blockIdx.y >> 1;
    const int half = blockIdx.y & 1;
    const int row0 = blockIdx.x * 128;

    __shared__ float As[32][129];   // [k][row] transposed, padded
    __shared__ float Bs[32][128];   // [k][col]

    const int tid = threadIdx.x;
    const int ty = tid >> 4;
    const int tx = tid & 15;

    float acc[8][8];
#pragma unroll
    for (int i = 0; i < 8; i++)
#pragma unroll
        for (int j = 0; j < 8; j++) acc[i][j] = 0.f;

    const float* Wbase = W + ((size_t)(head * 256 + half * 128)) * 128;

    for (int k0 = 0; k0 < 128; k0 += 32) {
#pragma unroll
        for (int i = 0; i < 16; i++) {
            int idx = tid + i * 256;
            int r = idx >> 5;
            int k = idx & 31;
            int gr = row0 + r;
            As[k][r] = (gr < NN) ? bond[(size_t)gr * 128 + k0 + k] : 0.f;
        }
#pragma unroll
        for (int i = 0; i < 16; i++) {
            int idx = tid + i * 256;
            int k = idx >> 7;
            int c = idx & 127;
            Bs[k][c] = Wbase[(size_t)(k0 + k) * 128 + c];
        }
        __syncthreads();

#pragma unroll
        for (int kk = 0; kk < 32; kk++) {
            float af[8], bf[8];
#pragma unroll
            for (int i = 0; i < 8; i++) af[i] = As[kk][ty * 8 + i];
#pragma unroll
            for (int j = 0; j < 8; j++) bf[j] = Bs[kk][tx * 8 + j];
#pragma unroll
            for (int i = 0; i < 8; i++)
#pragma unroll
                for (int j = 0; j < 8; j++)
                    acc[i][j] = fmaf(af[i], bf[j], acc[i][j]);
        }
        __syncthreads();
    }

    float* dstbuf = half ? g_P2 : g_P1;
    const float* bvec = bias + head * 128;
#pragma unroll
    for (int i = 0; i < 8; i++) {
        int gr = row0 + ty * 8 + i;
        if (gr >= NN) continue;
        float* orow = dstbuf + ((size_t)head * NN + gr) * 128 + tx * 8;
#pragma unroll
        for (int j = 0; j < 8; j++) {
            float v = acc[i][j];
            if (!half) v += bvec[tx * 8 + j];
            orow[j] = v;
        }
    }
}

// ---------------------------------------------------------------------------
// Edge phase: one warp per (edge, head).
//   alpha = tanh(P1[dst] + P2[src]); msg = alpha * bond[src];
//   out[dst][head*128 + :] += msg  via red.global.add.v4.f32
// ---------------------------------------------------------------------------
__global__ void edge_kernel(const float* __restrict__ bond,
                            const void* __restrict__ ei_raw,
                            float* __restrict__ out) {
    const int a = blockIdx.y;
    const int w = blockIdx.x * 8 + (threadIdx.x >> 5);
    if (w >= NE) return;
    const int lane = threadIdx.x & 31;

    int src, dst;
    if (g_is64) {
        const long long* base = (const long long*)ei_raw + (size_t)a * 2 * NE;
        src = (int)__ldg(&base[w]);
        dst = (int)__ldg(&base[NE + w]);
    } else {
        const int* base = (const int*)ei_raw + (size_t)a * 2 * NE;
        src = __ldg(&base[w]);
        dst = __ldg(&base[NE + w]);
    }

    const float4 p1 = *(const float4*)(g_P1 + ((size_t)a * NN + dst) * 128 + lane * 4);
    const float4 p2 = *(const float4*)(g_P2 + ((size_t)a * NN + src) * 128 + lane * 4);
    const float4 xj = *(const float4*)(bond + (size_t)src * 128 + lane * 4);

    float mx = tanhf(p1.x + p2.x) * xj.x;
    float my = tanhf(p1.y + p2.y) * xj.y;
    float mz = tanhf(p1.z + p2.z) * xj.z;
    float mw = tanhf(p1.w + p2.w) * xj.w;

    float* o = out + (size_t)dst * (NA * DD) + a * DD + lane * 4;
    asm volatile("red.global.add.v4.f32 [%0], {%1,%2,%3,%4};"
                 :: "l"(o), "f"(mx), "f"(my), "f"(mz), "f"(mw)
                 : "memory");
}

// ---------------------------------------------------------------------------
extern "C" void kernel_launch(void* const* d_in, const int* in_sizes, int n_in,
                              void* d_out, int out_size) {
    // Identify inputs by element count (robust to metadata ordering):
    //   bond_feat : 100000*128   = 12,800,000
    //   edge_index: 4*2*500000   =  4,000,000
    //   W         : 4*256*128    =    131,072
    //   b         : 4*128        =        512
    const float* bond = nullptr;
    const void*  ei   = nullptr;
    const float* W    = nullptr;
    const float* b    = nullptr;
    for (int i = 0; i < n_in; i++) {
        switch (in_sizes[i]) {
            case 12800000: bond = (const float*)d_in[i]; break;
            case 4000000:  ei   = d_in[i];               break;
            case 131072:   W    = (const float*)d_in[i]; break;
            case 512:      b    = (const float*)d_in[i]; break;
            default: break;
        }
    }
    float* out = (float*)d_out;   // [NN, NA*128] f32

    cudaMemsetAsync(out, 0, (size_t)out_size * sizeof(float));
    detect_kernel<<<1, 1>>>((const unsigned long long*)ei);
    proj_kernel<<<dim3((NN + 127) / 128, NA * 2), 256>>>(bond, W, b);
    edge_kernel<<<dim3((NE + 7) / 8, NA), 256>>>(bond, ei, out);
}

// round 3
// speedup vs baseline: 2.0339x; 2.0339x over previous
#include <cuda_runtime.h>
#include <math.h>

#define NN 100000   // nodes
#define NE 500000   // edges per head
#define NA 4        // angle heads
#define DD 128      // bond/hidden dim

// Scratch (allocation-guard-safe __device__ globals)
__device__ float g_P1[(size_t)NA * NN * DD];   // dst-side projection + bias
__device__ float g_P2[(size_t)NA * NN * DD];   // src-side projection
__device__ int   g_is64;                       // edge_index dtype flag

// ---------------------------------------------------------------------------
__global__ void detect_kernel(const unsigned long long* __restrict__ ei) {
    int ok = 1;
    for (int i = 0; i < 128; i++) {
        if (ei[i] >= (unsigned long long)NN) { ok = 0; break; }
    }
    g_is64 = ok;
}

__device__ __forceinline__ unsigned f2tf32(float v) {
    unsigned u;
    asm("cvt.rna.tf32.f32 %0, %1;" : "=r"(u) : "f"(v));
    return u;
}

// ---------------------------------------------------------------------------
// tf32 tensor-core projection.
// P[a][n][:] = bond[n] @ W[a][half*128 : +128][:] (+ b[a] if half==0)
// Block: 128x128 tile, 256 thr = 8 warps (4m x 2n), warp tile 32x64.
// K chunked by 32; mma.sync.m16n8k8.tf32.
// ---------------------------------------------------------------------------
__global__ void __launch_bounds__(256)
proj_tf32(const float* __restrict__ bond,
          const float* __restrict__ W,
          const float* __restrict__ bias) {
    const int head = blockIdx.y >> 1;
    const int half = blockIdx.y & 1;
    const int row0 = blockIdx.x * 128;

    __shared__ unsigned As[128][36];   // [m][k] pad 36: frag loads conflict-free
    __shared__ unsigned Bs[32][136];   // [k][n] pad 136: frag loads conflict-free

    const int tid  = threadIdx.x;
    const int lane = tid & 31;
    const int warp = tid >> 5;
    const int wm = warp & 3;           // 0..3 -> 32-row slice
    const int wn = warp >> 2;          // 0..1 -> 64-col slice
    const int g  = lane >> 2;          // group id 0..7
    const int tg = lane & 3;           // thread-in-group 0..3

    float acc[2][8][4];
#pragma unroll
    for (int mt = 0; mt < 2; mt++)
#pragma unroll
        for (int nt = 0; nt < 8; nt++)
#pragma unroll
            for (int i = 0; i < 4; i++) acc[mt][nt][i] = 0.f;

    const float* Wbase = W + (size_t)(head * 256 + half * 128) * 128;

    for (int kc = 0; kc < 4; kc++) {
        const int k0 = kc * 32;
        __syncthreads();
        // Load A chunk: 128 rows x 32 k (1024 float4s)
#pragma unroll
        for (int i = 0; i < 4; i++) {
            int f = tid + i * 256;
            int r = f >> 3, kq = f & 7;
            int grow = row0 + r;
            float4 v = make_float4(0.f, 0.f, 0.f, 0.f);
            if (grow < NN) v = *(const float4*)(bond + (size_t)grow * 128 + k0 + kq * 4);
            As[r][kq * 4 + 0] = f2tf32(v.x);
            As[r][kq * 4 + 1] = f2tf32(v.y);
            As[r][kq * 4 + 2] = f2tf32(v.z);
            As[r][kq * 4 + 3] = f2tf32(v.w);
        }
        // Load B chunk: 32 k x 128 n (1024 float4s)
#pragma unroll
        for (int i = 0; i < 4; i++) {
            int f = tid + i * 256;
            int k = f >> 5, nq = f & 31;
            float4 v = *(const float4*)(Wbase + (size_t)(k0 + k) * 128 + nq * 4);
            Bs[k][nq * 4 + 0] = f2tf32(v.x);
            Bs[k][nq * 4 + 1] = f2tf32(v.y);
            Bs[k][nq * 4 + 2] = f2tf32(v.z);
            Bs[k][nq * 4 + 3] = f2tf32(v.w);
        }
        __syncthreads();

#pragma unroll
        for (int ks = 0; ks < 4; ks++) {
            const int kb = ks * 8;
            unsigned bfr[8][2], afr[2][4];
#pragma unroll
            for (int nt = 0; nt < 8; nt++) {
                int n = wn * 64 + nt * 8 + g;
                bfr[nt][0] = Bs[kb + tg][n];
                bfr[nt][1] = Bs[kb + tg + 4][n];
            }
#pragma unroll
            for (int mt = 0; mt < 2; mt++) {
                int m = wm * 32 + mt * 16 + g;
                afr[mt][0] = As[m][kb + tg];
                afr[mt][1] = As[m + 8][kb + tg];
                afr[mt][2] = As[m][kb + tg + 4];
                afr[mt][3] = As[m + 8][kb + tg + 4];
            }
#pragma unroll
            for (int mt = 0; mt < 2; mt++)
#pragma unroll
                for (int nt = 0; nt < 8; nt++) {
                    asm volatile(
                        "mma.sync.aligned.m16n8k8.row.col.f32.tf32.tf32.f32 "
                        "{%0,%1,%2,%3}, {%4,%5,%6,%7}, {%8,%9}, {%0,%1,%2,%3};"
                        : "+f"(acc[mt][nt][0]), "+f"(acc[mt][nt][1]),
                          "+f"(acc[mt][nt][2]), "+f"(acc[mt][nt][3])
                        : "r"(afr[mt][0]), "r"(afr[mt][1]),
                          "r"(afr[mt][2]), "r"(afr[mt][3]),
                          "r"(bfr[nt][0]), "r"(bfr[nt][1]));
                }
        }
    }

    // Epilogue: c0,c1 -> row g, cols 2tg,2tg+1 ; c2,c3 -> row g+8
    float* dst = half ? g_P2 : g_P1;
    const float* bv = bias + head * 128;
#pragma unroll
    for (int mt = 0; mt < 2; mt++) {
#pragma unroll
        for (int nt = 0; nt < 8; nt++) {
            int c  = wn * 64 + nt * 8 + 2 * tg;
            float b0 = half ? 0.f : bv[c];
            float b1 = half ? 0.f : bv[c + 1];
            int r0 = row0 + wm * 32 + mt * 16 + g;
            if (r0 < NN) {
                float2 v = make_float2(acc[mt][nt][0] + b0, acc[mt][nt][1] + b1);
                *(float2*)(dst + ((size_t)head * NN + r0) * 128 + c) = v;
            }
            int r1 = r0 + 8;
            if (r1 < NN) {
                float2 v = make_float2(acc[mt][nt][2] + b0, acc[mt][nt][3] + b1);
                *(float2*)(dst + ((size_t)head * NN + r1) * 128 + c) = v;
            }
        }
    }
}

// ---------------------------------------------------------------------------
// Edge phase: one warp per (edge, head).
// ---------------------------------------------------------------------------
__global__ void edge_kernel(const float* __restrict__ bond,
                            const void* __restrict__ ei_raw,
                            float* __restrict__ out) {
    const int a = blockIdx.y;
    const int w = blockIdx.x * 8 + (threadIdx.x >> 5);
    if (w >= NE) return;
    const int lane = threadIdx.x & 31;

    int src, dst;
    if (g_is64) {
        const long long* base = (const long long*)ei_raw + (size_t)a * 2 * NE;
        src = (int)__ldg(&base[w]);
        dst = (int)__ldg(&base[NE + w]);
    } else {
        const int* base = (const int*)ei_raw + (size_t)a * 2 * NE;
        src = __ldg(&base[w]);
        dst = __ldg(&base[NE + w]);
    }

    const float4 p1 = *(const float4*)(g_P1 + ((size_t)a * NN + dst) * 128 + lane * 4);
    const float4 p2 = *(const float4*)(g_P2 + ((size_t)a * NN + src) * 128 + lane * 4);
    const float4 xj = *(const float4*)(bond + (size_t)src * 128 + lane * 4);

    float mx = tanhf(p1.x + p2.x) * xj.x;
    float my = tanhf(p1.y + p2.y) * xj.y;
    float mz = tanhf(p1.z + p2.z) * xj.z;
    float mw = tanhf(p1.w + p2.w) * xj.w;

    float* o = out + (size_t)dst * (NA * DD) + a * DD + lane * 4;
    asm volatile("red.global.add.v4.f32 [%0], {%1,%2,%3,%4};"
                 :: "l"(o), "f"(mx), "f"(my), "f"(mz), "f"(mw)
                 : "memory");
}

// ---------------------------------------------------------------------------
extern "C" void kernel_launch(void* const* d_in, const int* in_sizes, int n_in,
                              void* d_out, int out_size) {
    // Identify inputs by element count (robust to ordering)
    const float* bond = nullptr;
    const void*  ei   = nullptr;
    const float* W    = nullptr;
    const float* b    = nullptr;
    for (int i = 0; i < n_in; i++) {
        switch (in_sizes[i]) {
            case 12800000: bond = (const float*)d_in[i]; break;
            case 4000000:  ei   = d_in[i];               break;
            case 131072:   W    = (const float*)d_in[i]; break;
            case 512:      b    = (const float*)d_in[i]; break;
            default: break;
        }
    }
    float* out = (float*)d_out;   // [NN, NA*128] f32

    cudaMemsetAsync(out, 0, (size_t)out_size * sizeof(float));
    detect_kernel<<<1, 1>>>((const unsigned long long*)ei);
    proj_tf32<<<dim3((NN + 127) / 128, NA * 2), 256>>>(bond, W, b);
    edge_kernel<<<dim3((NE + 7) / 8, NA), 256>>>(bond, ei, out);
}

// round 4
// speedup vs baseline: 2.5683x; 1.2628x over previous
#include <cuda_runtime.h>
#include <math.h>

#define NN 100000   // nodes
#define NE 500000   // edges per head
#define NA 4        // angle heads
#define DD 128      // bond/hidden dim
#define NR (NA * NN)          // CSR rows (head-major)
#define NEDGE (NA * NE)       // total edges
#define SCAN_BLK 391          // ceil(NR / 1024)

// Scratch (allocation-guard-safe __device__ globals)
__device__ float g_P1[(size_t)NA * NN * DD];   // dst-side projection + bias
__device__ float g_P2[(size_t)NA * NN * DD];   // src-side projection
__device__ int   g_is64;                       // edge_index dtype flag
__device__ int   g_count[NR];
__device__ int   g_offs[NR + 1];
__device__ int   g_cursor[NR];
__device__ int   g_bsum[512];
__device__ int   g_srcs[NEDGE];                // dst-sorted src ids

// ---------------------------------------------------------------------------
__global__ void detect_kernel(const unsigned long long* __restrict__ ei) {
    int ok = 1;
    for (int i = 0; i < 128; i++)
        if (ei[i] >= (unsigned long long)NN) { ok = 0; break; }
    g_is64 = ok;
}

__device__ __forceinline__ unsigned f2tf32(float v) {
    unsigned u;
    asm("cvt.rna.tf32.f32 %0, %1;" : "=r"(u) : "f"(v));
    return u;
}

__device__ __forceinline__ void load_edge(const void* ei_raw, int a, int e,
                                          int& src, int& dst) {
    if (g_is64) {
        const long long* base = (const long long*)ei_raw + (size_t)a * 2 * NE;
        src = (int)__ldg(&base[e]);
        dst = (int)__ldg(&base[NE + e]);
    } else {
        const int* base = (const int*)ei_raw + (size_t)a * 2 * NE;
        src = __ldg(&base[e]);
        dst = __ldg(&base[NE + e]);
    }
}

// ---------------------------------------------------------------------------
// CSR build
// ---------------------------------------------------------------------------
__global__ void k_zero() {
    int i = blockIdx.x * blockDim.x + threadIdx.x;
    if (i < NR) g_count[i] = 0;
}

__global__ void k_hist(const void* __restrict__ ei_raw) {
    int i = blockIdx.x * blockDim.x + threadIdx.x;
    if (i >= NEDGE) return;
    int a = i / NE, e = i - a * NE;
    int src, dst;
    load_edge(ei_raw, a, e, src, dst);
    atomicAdd(&g_count[a * NN + dst], 1);
}

__global__ void __launch_bounds__(1024) k_scan1() {
    __shared__ int sh[1024];
    int t = threadIdx.x;
    int idx = blockIdx.x * 1024 + t;
    int v = (idx < NR) ? g_count[idx] : 0;
    sh[t] = v;
    __syncthreads();
#pragma unroll
    for (int d = 1; d < 1024; d <<= 1) {
        int x = (t >= d) ? sh[t - d] : 0;
        __syncthreads();
        sh[t] += x;
        __syncthreads();
    }
    if (idx < NR) g_offs[idx] = sh[t] - v;      // exclusive (local)
    if (t == 1023) g_bsum[blockIdx.x] = sh[t];  // block total
}

__global__ void __launch_bounds__(512) k_scan2() {
    __shared__ int sh[512];
    int t = threadIdx.x;
    int v = (t < SCAN_BLK) ? g_bsum[t] : 0;
    sh[t] = v;
    __syncthreads();
#pragma unroll
    for (int d = 1; d < 512; d <<= 1) {
        int x = (t >= d) ? sh[t - d] : 0;
        __syncthreads();
        sh[t] += x;
        __syncthreads();
    }
    if (t < SCAN_BLK) g_bsum[t] = sh[t] - v;    // exclusive block offsets
}

__global__ void __launch_bounds__(1024) k_scan3() {
    int i = blockIdx.x * 1024 + threadIdx.x;
    if (i < NR) {
        int o = g_offs[i] + g_bsum[blockIdx.x];
        g_offs[i] = o;
        g_cursor[i] = o;
    }
    if (i == 0) g_offs[NR] = NEDGE;
}

__global__ void k_scatter(const void* __restrict__ ei_raw) {
    int i = blockIdx.x * blockDim.x + threadIdx.x;
    if (i >= NEDGE) return;
    int a = i / NE, e = i - a * NE;
    int src, dst;
    load_edge(ei_raw, a, e, src, dst);
    int pos = atomicAdd(&g_cursor[a * NN + dst], 1);
    g_srcs[pos] = src;
}

// ---------------------------------------------------------------------------
// tf32 tensor-core projection (unchanged from R3).
// ---------------------------------------------------------------------------
__global__ void __launch_bounds__(256)
proj_tf32(const float* __restrict__ bond,
          const float* __restrict__ W,
          const float* __restrict__ bias) {
    const int head = blockIdx.y >> 1;
    const int half = blockIdx.y & 1;
    const int row0 = blockIdx.x * 128;

    __shared__ unsigned As[128][36];
    __shared__ unsigned Bs[32][136];

    const int tid  = threadIdx.x;
    const int lane = tid & 31;
    const int warp = tid >> 5;
    const int wm = warp & 3;
    const int wn = warp >> 2;
    const int g  = lane >> 2;
    const int tg = lane & 3;

    float acc[2][8][4];
#pragma unroll
    for (int mt = 0; mt < 2; mt++)
#pragma unroll
        for (int nt = 0; nt < 8; nt++)
#pragma unroll
            for (int i = 0; i < 4; i++) acc[mt][nt][i] = 0.f;

    const float* Wbase = W + (size_t)(head * 256 + half * 128) * 128;

    for (int kc = 0; kc < 4; kc++) {
        const int k0 = kc * 32;
        __syncthreads();
#pragma unroll
        for (int i = 0; i < 4; i++) {
            int f = tid + i * 256;
            int r = f >> 3, kq = f & 7;
            int grow = row0 + r;
            float4 v = make_float4(0.f, 0.f, 0.f, 0.f);
            if (grow < NN) v = *(const float4*)(bond + (size_t)grow * 128 + k0 + kq * 4);
            As[r][kq * 4 + 0] = f2tf32(v.x);
            As[r][kq * 4 + 1] = f2tf32(v.y);
            As[r][kq * 4 + 2] = f2tf32(v.z);
            As[r][kq * 4 + 3] = f2tf32(v.w);
        }
#pragma unroll
        for (int i = 0; i < 4; i++) {
            int f = tid + i * 256;
            int k = f >> 5, nq = f & 31;
            float4 v = *(const float4*)(Wbase + (size_t)(k0 + k) * 128 + nq * 4);
            Bs[k][nq * 4 + 0] = f2tf32(v.x);
            Bs[k][nq * 4 + 1] = f2tf32(v.y);
            Bs[k][nq * 4 + 2] = f2tf32(v.z);
            Bs[k][nq * 4 + 3] = f2tf32(v.w);
        }
        __syncthreads();

#pragma unroll
        for (int ks = 0; ks < 4; ks++) {
            const int kb = ks * 8;
            unsigned bfr[8][2], afr[2][4];
#pragma unroll
            for (int nt = 0; nt < 8; nt++) {
                int n = wn * 64 + nt * 8 + g;
                bfr[nt][0] = Bs[kb + tg][n];
                bfr[nt][1] = Bs[kb + tg + 4][n];
            }
#pragma unroll
            for (int mt = 0; mt < 2; mt++) {
                int m = wm * 32 + mt * 16 + g;
                afr[mt][0] = As[m][kb + tg];
                afr[mt][1] = As[m + 8][kb + tg];
                afr[mt][2] = As[m][kb + tg + 4];
                afr[mt][3] = As[m + 8][kb + tg + 4];
            }
#pragma unroll
            for (int mt = 0; mt < 2; mt++)
#pragma unroll
                for (int nt = 0; nt < 8; nt++) {
                    asm volatile(
                        "mma.sync.aligned.m16n8k8.row.col.f32.tf32.tf32.f32 "
                        "{%0,%1,%2,%3}, {%4,%5,%6,%7}, {%8,%9}, {%0,%1,%2,%3};"
                        : "+f"(acc[mt][nt][0]), "+f"(acc[mt][nt][1]),
                          "+f"(acc[mt][nt][2]), "+f"(acc[mt][nt][3])
                        : "r"(afr[mt][0]), "r"(afr[mt][1]),
                          "r"(afr[mt][2]), "r"(afr[mt][3]),
                          "r"(bfr[nt][0]), "r"(bfr[nt][1]));
                }
        }
    }

    float* dst = half ? g_P2 : g_P1;
    const float* bv = bias + head * 128;
#pragma unroll
    for (int mt = 0; mt < 2; mt++) {
#pragma unroll
        for (int nt = 0; nt < 8; nt++) {
            int c  = wn * 64 + nt * 8 + 2 * tg;
            float b0 = half ? 0.f : bv[c];
            float b1 = half ? 0.f : bv[c + 1];
            int r0 = row0 + wm * 32 + mt * 16 + g;
            if (r0 < NN) {
                float2 v = make_float2(acc[mt][nt][0] + b0, acc[mt][nt][1] + b1);
                *(float2*)(dst + ((size_t)head * NN + r0) * 128 + c) = v;
            }
            int r1 = r0 + 8;
            if (r1 < NN) {
                float2 v = make_float2(acc[mt][nt][2] + b0, acc[mt][nt][3] + b1);
                *(float2*)(dst + ((size_t)head * NN + r1) * 128 + c) = v;
            }
        }
    }
}

// ---------------------------------------------------------------------------
// Gather-reduce: one warp per (node, head). No atomics, single store per row.
// ---------------------------------------------------------------------------
__global__ void __launch_bounds__(256)
edge_gather(const float* __restrict__ bond, float* __restrict__ out) {
    const int a = blockIdx.y;
    const int node = blockIdx.x * 8 + (threadIdx.x >> 5);
    if (node >= NN) return;
    const int lane = threadIdx.x & 31;

    const int r = a * NN + node;
    const int e0 = __ldg(&g_offs[r]);
    const int e1 = __ldg(&g_offs[r + 1]);

    float4 acc = make_float4(0.f, 0.f, 0.f, 0.f);

    if (e0 < e1) {
        const float4 p1 = *(const float4*)(g_P1 + (size_t)r * 128 + lane * 4);
        int s = __ldg(&g_srcs[e0]);
        for (int e = e0; e < e1; e++) {
            int snext = (e + 1 < e1) ? __ldg(&g_srcs[e + 1]) : 0;
            const float4 p2 = *(const float4*)(g_P2 + ((size_t)a * NN + s) * 128 + lane * 4);
            const float4 xj = *(const float4*)(bond + (size_t)s * 128 + lane * 4);
            acc.x += tanhf(p1.x + p2.x) * xj.x;
            acc.y += tanhf(p1.y + p2.y) * xj.y;
            acc.z += tanhf(p1.z + p2.z) * xj.z;
            acc.w += tanhf(p1.w + p2.w) * xj.w;
            s = snext;
        }
    }
    *(float4*)(out + (size_t)node * (NA * DD) + a * DD + lane * 4) = acc;
}

// ---------------------------------------------------------------------------
extern "C" void kernel_launch(void* const* d_in, const int* in_sizes, int n_in,
                              void* d_out, int out_size) {
    const float* bond = nullptr;
    const void*  ei   = nullptr;
    const float* W    = nullptr;
    const float* b    = nullptr;
    for (int i = 0; i < n_in; i++) {
        switch (in_sizes[i]) {
            case 12800000: bond = (const float*)d_in[i]; break;
            case 4000000:  ei   = d_in[i];               break;
            case 131072:   W    = (const float*)d_in[i]; break;
            case 512:      b    = (const float*)d_in[i]; break;
            default: break;
        }
    }
    float* out = (float*)d_out;   // [NN, NA*128] f32 — fully written by edge_gather

    detect_kernel<<<1, 1>>>((const unsigned long long*)ei);

    // CSR build
    k_zero<<<(NR + 255) / 256, 256>>>();
    k_hist<<<(NEDGE + 255) / 256, 256>>>(ei);
    k_scan1<<<SCAN_BLK, 1024>>>();
    k_scan2<<<1, 512>>>();
    k_scan3<<<SCAN_BLK, 1024>>>();
    k_scatter<<<(NEDGE + 255) / 256, 256>>>(ei);

    // Projection (independent of CSR; stream-ordered after, overlap not needed)
    proj_tf32<<<dim3((NN + 127) / 128, NA * 2), 256>>>(bond, W, b);

    // Fused gather-reduce
    edge_gather<<<dim3((NN + 7) / 8, NA), 256>>>(bond, out);
}

// round 5
// speedup vs baseline: 2.7819x; 1.0832x over previous
#include <cuda_runtime.h>
#include <math.h>

#define NN 100000   // nodes
#define NE 500000   // edges per head
#define NA 4        // angle heads
#define DD 128      // bond/hidden dim
#define NR (NA * NN)          // CSR rows (head-major)
#define NEDGE (NA * NE)       // total edges
#define SCAN_BLK 391          // ceil(NR / 1024)

// Scratch (allocation-guard-safe __device__ globals)
__device__ float g_P1[(size_t)NA * NN * DD];   // dst-side projection + bias
__device__ float g_P2[(size_t)NA * NN * DD];   // src-side projection
__device__ int   g_is64;                       // edge_index dtype flag
__device__ int   g_count[NR];
__device__ int   g_offs[NR + 1];
__device__ int   g_cursor[NR];
__device__ int   g_bsum[512];
__device__ int   g_srcs[NEDGE];                // dst-sorted src ids

// ---------------------------------------------------------------------------
__global__ void detect_kernel(const unsigned long long* __restrict__ ei) {
    int ok = 1;
    for (int i = 0; i < 128; i++)
        if (ei[i] >= (unsigned long long)NN) { ok = 0; break; }
    g_is64 = ok;
}

__device__ __forceinline__ unsigned f2tf32(float v) {
    unsigned u;
    asm("cvt.rna.tf32.f32 %0, %1;" : "=r"(u) : "f"(v));
    return u;
}

__device__ __forceinline__ float tanh_fast(float x) {
    float y;
    asm("tanh.approx.f32 %0, %1;" : "=f"(y) : "f"(x));
    return y;
}

__device__ __forceinline__ void load_edge(const void* ei_raw, int a, int e,
                                          int& src, int& dst) {
    if (g_is64) {
        const long long* base = (const long long*)ei_raw + (size_t)a * 2 * NE;
        src = (int)__ldg(&base[e]);
        dst = (int)__ldg(&base[NE + e]);
    } else {
        const int* base = (const int*)ei_raw + (size_t)a * 2 * NE;
        src = __ldg(&base[e]);
        dst = __ldg(&base[NE + e]);
    }
}

// ---------------------------------------------------------------------------
// CSR build
// ---------------------------------------------------------------------------
__global__ void k_zero() {
    int i = blockIdx.x * blockDim.x + threadIdx.x;
    if (i < NR) g_count[i] = 0;
}

__global__ void k_hist(const void* __restrict__ ei_raw) {
    int i = blockIdx.x * blockDim.x + threadIdx.x;
    if (i >= NEDGE) return;
    int a = i / NE, e = i - a * NE;
    int src, dst;
    load_edge(ei_raw, a, e, src, dst);
    atomicAdd(&g_count[a * NN + dst], 1);
}

__global__ void __launch_bounds__(1024) k_scan1() {
    __shared__ int sh[1024];
    int t = threadIdx.x;
    int idx = blockIdx.x * 1024 + t;
    int v = (idx < NR) ? g_count[idx] : 0;
    sh[t] = v;
    __syncthreads();
#pragma unroll
    for (int d = 1; d < 1024; d <<= 1) {
        int x = (t >= d) ? sh[t - d] : 0;
        __syncthreads();
        sh[t] += x;
        __syncthreads();
    }
    if (idx < NR) g_offs[idx] = sh[t] - v;      // exclusive (local)
    if (t == 1023) g_bsum[blockIdx.x] = sh[t];  // block total
}

__global__ void __launch_bounds__(512) k_scan2() {
    __shared__ int sh[512];
    int t = threadIdx.x;
    int v = (t < SCAN_BLK) ? g_bsum[t] : 0;
    sh[t] = v;
    __syncthreads();
#pragma unroll
    for (int d = 1; d < 512; d <<= 1) {
        int x = (t >= d) ? sh[t - d] : 0;
        __syncthreads();
        sh[t] += x;
        __syncthreads();
    }
    if (t < SCAN_BLK) g_bsum[t] = sh[t] - v;    // exclusive block offsets
}

__global__ void __launch_bounds__(1024) k_scan3() {
    int i = blockIdx.x * 1024 + threadIdx.x;
    if (i < NR) {
        int o = g_offs[i] + g_bsum[blockIdx.x];
        g_offs[i] = o;
        g_cursor[i] = o;
    }
    if (i == 0) g_offs[NR] = NEDGE;
}

__global__ void k_scatter(const void* __restrict__ ei_raw) {
    int i = blockIdx.x * blockDim.x + threadIdx.x;
    if (i >= NEDGE) return;
    int a = i / NE, e = i - a * NE;
    int src, dst;
    load_edge(ei_raw, a, e, src, dst);
    int pos = atomicAdd(&g_cursor[a * NN + dst], 1);
    g_srcs[pos] = src;
}

// ---------------------------------------------------------------------------
// tf32 tensor-core projection (unchanged).
// ---------------------------------------------------------------------------
__global__ void __launch_bounds__(256)
proj_tf32(const float* __restrict__ bond,
          const float* __restrict__ W,
          const float* __restrict__ bias) {
    const int head = blockIdx.y >> 1;
    const int half = blockIdx.y & 1;
    const int row0 = blockIdx.x * 128;

    __shared__ unsigned As[128][36];
    __shared__ unsigned Bs[32][136];

    const int tid  = threadIdx.x;
    const int lane = tid & 31;
    const int warp = tid >> 5;
    const int wm = warp & 3;
    const int wn = warp >> 2;
    const int g  = lane >> 2;
    const int tg = lane & 3;

    float acc[2][8][4];
#pragma unroll
    for (int mt = 0; mt < 2; mt++)
#pragma unroll
        for (int nt = 0; nt < 8; nt++)
#pragma unroll
            for (int i = 0; i < 4; i++) acc[mt][nt][i] = 0.f;

    const float* Wbase = W + (size_t)(head * 256 + half * 128) * 128;

    for (int kc = 0; kc < 4; kc++) {
        const int k0 = kc * 32;
        __syncthreads();
#pragma unroll
        for (int i = 0; i < 4; i++) {
            int f = tid + i * 256;
            int r = f >> 3, kq = f & 7;
            int grow = row0 + r;
            float4 v = make_float4(0.f, 0.f, 0.f, 0.f);
            if (grow < NN) v = *(const float4*)(bond + (size_t)grow * 128 + k0 + kq * 4);
            As[r][kq * 4 + 0] = f2tf32(v.x);
            As[r][kq * 4 + 1] = f2tf32(v.y);
            As[r][kq * 4 + 2] = f2tf32(v.z);
            As[r][kq * 4 + 3] = f2tf32(v.w);
        }
#pragma unroll
        for (int i = 0; i < 4; i++) {
            int f = tid + i * 256;
            int k = f >> 5, nq = f & 31;
            float4 v = *(const float4*)(Wbase + (size_t)(k0 + k) * 128 + nq * 4);
            Bs[k][nq * 4 + 0] = f2tf32(v.x);
            Bs[k][nq * 4 + 1] = f2tf32(v.y);
            Bs[k][nq * 4 + 2] = f2tf32(v.z);
            Bs[k][nq * 4 + 3] = f2tf32(v.w);
        }
        __syncthreads();

#pragma unroll
        for (int ks = 0; ks < 4; ks++) {
            const int kb = ks * 8;
            unsigned bfr[8][2], afr[2][4];
#pragma unroll
            for (int nt = 0; nt < 8; nt++) {
                int n = wn * 64 + nt * 8 + g;
                bfr[nt][0] = Bs[kb + tg][n];
                bfr[nt][1] = Bs[kb + tg + 4][n];
            }
#pragma unroll
            for (int mt = 0; mt < 2; mt++) {
                int m = wm * 32 + mt * 16 + g;
                afr[mt][0] = As[m][kb + tg];
                afr[mt][1] = As[m + 8][kb + tg];
                afr[mt][2] = As[m][kb + tg + 4];
                afr[mt][3] = As[m + 8][kb + tg + 4];
            }
#pragma unroll
            for (int mt = 0; mt < 2; mt++)
#pragma unroll
                for (int nt = 0; nt < 8; nt++) {
                    asm volatile(
                        "mma.sync.aligned.m16n8k8.row.col.f32.tf32.tf32.f32 "
                        "{%0,%1,%2,%3}, {%4,%5,%6,%7}, {%8,%9}, {%0,%1,%2,%3};"
                        : "+f"(acc[mt][nt][0]), "+f"(acc[mt][nt][1]),
                          "+f"(acc[mt][nt][2]), "+f"(acc[mt][nt][3])
                        : "r"(afr[mt][0]), "r"(afr[mt][1]),
                          "r"(afr[mt][2]), "r"(afr[mt][3]),
                          "r"(bfr[nt][0]), "r"(bfr[nt][1]));
                }
        }
    }

    float* dst = half ? g_P2 : g_P1;
    const float* bv = bias + head * 128;
#pragma unroll
    for (int mt = 0; mt < 2; mt++) {
#pragma unroll
        for (int nt = 0; nt < 8; nt++) {
            int c  = wn * 64 + nt * 8 + 2 * tg;
            float b0 = half ? 0.f : bv[c];
            float b1 = half ? 0.f : bv[c + 1];
            int r0 = row0 + wm * 32 + mt * 16 + g;
            if (r0 < NN) {
                float2 v = make_float2(acc[mt][nt][0] + b0, acc[mt][nt][1] + b1);
                *(float2*)(dst + ((size_t)head * NN + r0) * 128 + c) = v;
            }
            int r1 = r0 + 8;
            if (r1 < NN) {
                float2 v = make_float2(acc[mt][nt][2] + b0, acc[mt][nt][3] + b1);
                *(float2*)(dst + ((size_t)head * NN + r1) * 128 + c) = v;
            }
        }
    }
}

// ---------------------------------------------------------------------------
// Gather-reduce: one warp per (node, head). tanh.approx + 2x unrolled gathers.
// ---------------------------------------------------------------------------
__global__ void __launch_bounds__(256)
edge_gather(const float* __restrict__ bond, float* __restrict__ out) {
    const int a = blockIdx.y;
    const int node = blockIdx.x * 8 + (threadIdx.x >> 5);
    if (node >= NN) return;
    const int lane = threadIdx.x & 31;

    const int r = a * NN + node;
    const int e0 = __ldg(&g_offs[r]);
    const int e1 = __ldg(&g_offs[r + 1]);

    float4 acc = make_float4(0.f, 0.f, 0.f, 0.f);

    if (e0 < e1) {
        const float4 p1 = *(const float4*)(g_P1 + (size_t)r * 128 + lane * 4);
        const float* P2h = g_P2 + (size_t)a * NN * 128;

        int e = e0;
        // 2x unrolled main loop: 6 outstanding 512B gathers per iteration
        for (; e + 1 < e1; e += 2) {
            int s0 = __ldg(&g_srcs[e]);
            int s1 = __ldg(&g_srcs[e + 1]);
            const float4 p2a = *(const float4*)(P2h + (size_t)s0 * 128 + lane * 4);
            const float4 xja = *(const float4*)(bond + (size_t)s0 * 128 + lane * 4);
            const float4 p2b = *(const float4*)(P2h + (size_t)s1 * 128 + lane * 4);
            const float4 xjb = *(const float4*)(bond + (size_t)s1 * 128 + lane * 4);
            acc.x += tanh_fast(p1.x + p2a.x) * xja.x;
            acc.y += tanh_fast(p1.y + p2a.y) * xja.y;
            acc.z += tanh_fast(p1.z + p2a.z) * xja.z;
            acc.w += tanh_fast(p1.w + p2a.w) * xja.w;
            acc.x += tanh_fast(p1.x + p2b.x) * xjb.x;
            acc.y += tanh_fast(p1.y + p2b.y) * xjb.y;
            acc.z += tanh_fast(p1.z + p2b.z) * xjb.z;
            acc.w += tanh_fast(p1.w + p2b.w) * xjb.w;
        }
        if (e < e1) {
            int s = __ldg(&g_srcs[e]);
            const float4 p2 = *(const float4*)(P2h + (size_t)s * 128 + lane * 4);
            const float4 xj = *(const float4*)(bond + (size_t)s * 128 + lane * 4);
            acc.x += tanh_fast(p1.x + p2.x) * xj.x;
            acc.y += tanh_fast(p1.y + p2.y) * xj.y;
            acc.z += tanh_fast(p1.z + p2.z) * xj.z;
            acc.w += tanh_fast(p1.w + p2.w) * xj.w;
        }
    }
    *(float4*)(out + (size_t)node * (NA * DD) + a * DD + lane * 4) = acc;
}

// ---------------------------------------------------------------------------
extern "C" void kernel_launch(void* const* d_in, const int* in_sizes, int n_in,
                              void* d_out, int out_size) {
    const float* bond = nullptr;
    const void*  ei   = nullptr;
    const float* W    = nullptr;
    const float* b    = nullptr;
    for (int i = 0; i < n_in; i++) {
        switch (in_sizes[i]) {
            case 12800000: bond = (const float*)d_in[i]; break;
            case 4000000:  ei   = d_in[i];               break;
            case 131072:   W    = (const float*)d_in[i]; break;
            case 512:      b    = (const float*)d_in[i]; break;
            default: break;
        }
    }
    float* out = (float*)d_out;   // [NN, NA*128] f32 — fully written by edge_gather

    detect_kernel<<<1, 1>>>((const unsigned long long*)ei);

    // CSR build
    k_zero<<<(NR + 255) / 256, 256>>>();
    k_hist<<<(NEDGE + 255) / 256, 256>>>(ei);
    k_scan1<<<SCAN_BLK, 1024>>>();
    k_scan2<<<1, 512>>>();
    k_scan3<<<SCAN_BLK, 1024>>>();
    k_scatter<<<(NEDGE + 255) / 256, 256>>>(ei);

    // Projection
    proj_tf32<<<dim3((NN + 127) / 128, NA * 2), 256>>>(bond, W, b);

    // Fused gather-reduce
    edge_gather<<<dim3((NN + 7) / 8, NA), 256>>>(bond, out);
}

// round 6
// speedup vs baseline: 2.8432x; 1.0220x over previous
#include <cuda_runtime.h>
#include <math.h>

#define NN 100000   // nodes
#define NE 500000   // edges per head
#define NA 4        // angle heads
#define DD 128      // bond/hidden dim
#define NR (NA * NN)          // CSR rows (head-major)
#define NEDGE (NA * NE)       // total edges
#define SCAN_BLK 391          // ceil(NR / 1024)

// Scratch (allocation-guard-safe __device__ globals)
__device__ float g_P1[(size_t)NA * NN * DD];   // dst-side projection + bias
__device__ float g_P2[(size_t)NA * NN * DD];   // src-side projection
__device__ int   g_is64;                       // edge_index dtype flag
__device__ int   g_count[NR];
__device__ int   g_offs[NR + 1];
__device__ int   g_cursor[NR];
__device__ int   g_bsum[512];
__device__ int   g_srcs[NEDGE];                // dst-sorted src ids

// ---------------------------------------------------------------------------
__global__ void detect_kernel(const unsigned long long* __restrict__ ei) {
    int ok = 1;
    for (int i = 0; i < 128; i++)
        if (ei[i] >= (unsigned long long)NN) { ok = 0; break; }
    g_is64 = ok;
}

__device__ __forceinline__ unsigned f2tf32(float v) {
    unsigned u;
    asm("cvt.rna.tf32.f32 %0, %1;" : "=r"(u) : "f"(v));
    return u;
}

__device__ __forceinline__ float tanh_fast(float x) {
    float y;
    asm("tanh.approx.f32 %0, %1;" : "=f"(y) : "f"(x));
    return y;
}

__device__ __forceinline__ void load_edge(const void* ei_raw, int a, int e,
                                          int& src, int& dst) {
    if (g_is64) {
        const long long* base = (const long long*)ei_raw + (size_t)a * 2 * NE;
        src = (int)__ldg(&base[e]);
        dst = (int)__ldg(&base[NE + e]);
    } else {
        const int* base = (const int*)ei_raw + (size_t)a * 2 * NE;
        src = __ldg(&base[e]);
        dst = __ldg(&base[NE + e]);
    }
}

// ---------------------------------------------------------------------------
// CSR build
// ---------------------------------------------------------------------------
__global__ void k_zero() {
    int i = blockIdx.x * blockDim.x + threadIdx.x;
    if (i < NR) g_count[i] = 0;
}

__global__ void k_hist(const void* __restrict__ ei_raw) {
    int i = blockIdx.x * blockDim.x + threadIdx.x;
    if (i >= NEDGE) return;
    int a = i / NE, e = i - a * NE;
    int src, dst;
    load_edge(ei_raw, a, e, src, dst);
    atomicAdd(&g_count[a * NN + dst], 1);
}

__global__ void __launch_bounds__(1024) k_scan1() {
    __shared__ int sh[1024];
    int t = threadIdx.x;
    int idx = blockIdx.x * 1024 + t;
    int v = (idx < NR) ? g_count[idx] : 0;
    sh[t] = v;
    __syncthreads();
#pragma unroll
    for (int d = 1; d < 1024; d <<= 1) {
        int x = (t >= d) ? sh[t - d] : 0;
        __syncthreads();
        sh[t] += x;
        __syncthreads();
    }
    if (idx < NR) g_offs[idx] = sh[t] - v;
    if (t == 1023) g_bsum[blockIdx.x] = sh[t];
}

__global__ void __launch_bounds__(512) k_scan2() {
    __shared__ int sh[512];
    int t = threadIdx.x;
    int v = (t < SCAN_BLK) ? g_bsum[t] : 0;
    sh[t] = v;
    __syncthreads();
#pragma unroll
    for (int d = 1; d < 512; d <<= 1) {
        int x = (t >= d) ? sh[t - d] : 0;
        __syncthreads();
        sh[t] += x;
        __syncthreads();
    }
    if (t < SCAN_BLK) g_bsum[t] = sh[t] - v;
}

__global__ void __launch_bounds__(1024) k_scan3() {
    int i = blockIdx.x * 1024 + threadIdx.x;
    if (i < NR) {
        int o = g_offs[i] + g_bsum[blockIdx.x];
        g_offs[i] = o;
        g_cursor[i] = o;
    }
    if (i == 0) g_offs[NR] = NEDGE;
}

__global__ void k_scatter(const void* __restrict__ ei_raw) {
    int i = blockIdx.x * blockDim.x + threadIdx.x;
    if (i >= NEDGE) return;
    int a = i / NE, e = i - a * NE;
    int src, dst;
    load_edge(ei_raw, a, e, src, dst);
    int pos = atomicAdd(&g_cursor[a * NN + dst], 1);
    g_srcs[pos] = src;
}

// ---------------------------------------------------------------------------
// Fused tf32 projection: one block owns a 128-row A-tile (loaded to smem ONCE,
// full K=128) and loops over all 8 (head,half) W-slices.
// Dynamic smem: As 128x132 u32 (67.6KB) + Bs 32x136 u32 (17.4KB) = 85KB.
// ---------------------------------------------------------------------------
__global__ void __launch_bounds__(256)
proj_fused(const float* __restrict__ bond,
           const float* __restrict__ W,
           const float* __restrict__ bias) {
    extern __shared__ unsigned smem[];
    unsigned (*As)[132] = (unsigned (*)[132])smem;                // [128][132]
    unsigned (*Bs)[136] = (unsigned (*)[136])(smem + 128 * 132);  // [32][136]

    const int row0 = blockIdx.x * 128;
    const int tid  = threadIdx.x;
    const int lane = tid & 31;
    const int warp = tid >> 5;
    const int wm = warp & 3;
    const int wn = warp >> 2;
    const int g  = lane >> 2;
    const int tg = lane & 3;

    // Load full A tile: 128 rows x 128 k = 4096 float4 loads (16/thread)
#pragma unroll
    for (int i = 0; i < 16; i++) {
        int f = tid + i * 256;
        int r = f >> 5, c4 = f & 31;
        int grow = row0 + r;
        float4 v = make_float4(0.f, 0.f, 0.f, 0.f);
        if (grow < NN) v = *(const float4*)(bond + (size_t)grow * 128 + c4 * 4);
        uint4 u = make_uint4(f2tf32(v.x), f2tf32(v.y), f2tf32(v.z), f2tf32(v.w));
        *(uint4*)(&As[r][c4 * 4]) = u;   // row pitch 528B = 33*16, aligned
    }

    for (int combo = 0; combo < NA * 2; combo++) {
        const int head = combo >> 1;
        const int half = combo & 1;
        const float* Wbase = W + (size_t)(head * 256 + half * 128) * 128;

        float acc[2][8][4];
#pragma unroll
        for (int mt = 0; mt < 2; mt++)
#pragma unroll
            for (int nt = 0; nt < 8; nt++)
#pragma unroll
                for (int i = 0; i < 4; i++) acc[mt][nt][i] = 0.f;

        for (int kc = 0; kc < 4; kc++) {
            const int k0 = kc * 32;
            __syncthreads();
#pragma unroll
            for (int i = 0; i < 4; i++) {
                int f = tid + i * 256;
                int k = f >> 5, nq = f & 31;
                float4 v = *(const float4*)(Wbase + (size_t)(k0 + k) * 128 + nq * 4);
                Bs[k][nq * 4 + 0] = f2tf32(v.x);
                Bs[k][nq * 4 + 1] = f2tf32(v.y);
                Bs[k][nq * 4 + 2] = f2tf32(v.z);
                Bs[k][nq * 4 + 3] = f2tf32(v.w);
            }
            __syncthreads();

#pragma unroll
            for (int ks = 0; ks < 4; ks++) {
                const int kb = ks * 8;
                unsigned bfr[8][2], afr[2][4];
#pragma unroll
                for (int nt = 0; nt < 8; nt++) {
                    int n = wn * 64 + nt * 8 + g;
                    bfr[nt][0] = Bs[kb + tg][n];
                    bfr[nt][1] = Bs[kb + tg + 4][n];
                }
#pragma unroll
                for (int mt = 0; mt < 2; mt++) {
                    int m = wm * 32 + mt * 16 + g;
                    afr[mt][0] = As[m][k0 + kb + tg];
                    afr[mt][1] = As[m + 8][k0 + kb + tg];
                    afr[mt][2] = As[m][k0 + kb + tg + 4];
                    afr[mt][3] = As[m + 8][k0 + kb + tg + 4];
                }
#pragma unroll
                for (int mt = 0; mt < 2; mt++)
#pragma unroll
                    for (int nt = 0; nt < 8; nt++) {
                        asm volatile(
                            "mma.sync.aligned.m16n8k8.row.col.f32.tf32.tf32.f32 "
                            "{%0,%1,%2,%3}, {%4,%5,%6,%7}, {%8,%9}, {%0,%1,%2,%3};"
                            : "+f"(acc[mt][nt][0]), "+f"(acc[mt][nt][1]),
                              "+f"(acc[mt][nt][2]), "+f"(acc[mt][nt][3])
                            : "r"(afr[mt][0]), "r"(afr[mt][1]),
                              "r"(afr[mt][2]), "r"(afr[mt][3]),
                              "r"(bfr[nt][0]), "r"(bfr[nt][1]));
                    }
            }
        }

        float* dst = half ? g_P2 : g_P1;
        const float* bv = bias + head * 128;
#pragma unroll
        for (int mt = 0; mt < 2; mt++) {
#pragma unroll
            for (int nt = 0; nt < 8; nt++) {
                int c  = wn * 64 + nt * 8 + 2 * tg;
                float b0 = half ? 0.f : bv[c];
                float b1 = half ? 0.f : bv[c + 1];
                int r0 = row0 + wm * 32 + mt * 16 + g;
                if (r0 < NN) {
                    float2 v = make_float2(acc[mt][nt][0] + b0, acc[mt][nt][1] + b1);
                    *(float2*)(dst + ((size_t)head * NN + r0) * 128 + c) = v;
                }
                int r1 = r0 + 8;
                if (r1 < NN) {
                    float2 v = make_float2(acc[mt][nt][2] + b0, acc[mt][nt][3] + b1);
                    *(float2*)(dst + ((size_t)head * NN + r1) * 128 + c) = v;
                }
            }
        }
    }
}

// ---------------------------------------------------------------------------
// Gather-reduce: one warp per (node, head).
// ---------------------------------------------------------------------------
__global__ void __launch_bounds__(256)
edge_gather(const float* __restrict__ bond, float* __restrict__ out) {
    const int a = blockIdx.y;
    const int node = blockIdx.x * 8 + (threadIdx.x >> 5);
    if (node >= NN) return;
    const int lane = threadIdx.x & 31;

    const int r = a * NN + node;
    const int e0 = __ldg(&g_offs[r]);
    const int e1 = __ldg(&g_offs[r + 1]);

    float4 acc = make_float4(0.f, 0.f, 0.f, 0.f);

    if (e0 < e1) {
        const float4 p1 = *(const float4*)(g_P1 + (size_t)r * 128 + lane * 4);
        const float* P2h = g_P2 + (size_t)a * NN * 128;

        int e = e0;
        for (; e + 1 < e1; e += 2) {
            int s0 = __ldg(&g_srcs[e]);
            int s1 = __ldg(&g_srcs[e + 1]);
            const float4 p2a = *(const float4*)(P2h + (size_t)s0 * 128 + lane * 4);
            const float4 xja = *(const float4*)(bond + (size_t)s0 * 128 + lane * 4);
            const float4 p2b = *(const float4*)(P2h + (size_t)s1 * 128 + lane * 4);
            const float4 xjb = *(const float4*)(bond + (size_t)s1 * 128 + lane * 4);
            acc.x += tanh_fast(p1.x + p2a.x) * xja.x;
            acc.y += tanh_fast(p1.y + p2a.y) * xja.y;
            acc.z += tanh_fast(p1.z + p2a.z) * xja.z;
            acc.w += tanh_fast(p1.w + p2a.w) * xja.w;
            acc.x += tanh_fast(p1.x + p2b.x) * xjb.x;
            acc.y += tanh_fast(p1.y + p2b.y) * xjb.y;
            acc.z += tanh_fast(p1.z + p2b.z) * xjb.z;
            acc.w += tanh_fast(p1.w + p2b.w) * xjb.w;
        }
        if (e < e1) {
            int s = __ldg(&g_srcs[e]);
            const float4 p2 = *(const float4*)(P2h + (size_t)s * 128 + lane * 4);
            const float4 xj = *(const float4*)(bond + (size_t)s * 128 + lane * 4);
            acc.x += tanh_fast(p1.x + p2.x) * xj.x;
            acc.y += tanh_fast(p1.y + p2.y) * xj.y;
            acc.z += tanh_fast(p1.z + p2.z) * xj.z;
            acc.w += tanh_fast(p1.w + p2.w) * xj.w;
        }
    }
    *(float4*)(out + (size_t)node * (NA * DD) + a * DD + lane * 4) = acc;
}

// ---------------------------------------------------------------------------
extern "C" void kernel_launch(void* const* d_in, const int* in_sizes, int n_in,
                              void* d_out, int out_size) {
    const float* bond = nullptr;
    const void*  ei   = nullptr;
    const float* W    = nullptr;
    const float* b    = nullptr;
    for (int i = 0; i < n_in; i++) {
        switch (in_sizes[i]) {
            case 12800000: bond = (const float*)d_in[i]; break;
            case 4000000:  ei   = d_in[i];               break;
            case 131072:   W    = (const float*)d_in[i]; break;
            case 512:      b    = (const float*)d_in[i]; break;
            default: break;
        }
    }
    float* out = (float*)d_out;   // [NN, NA*128] f32 — fully written by edge_gather

    const int PROJ_SMEM = (128 * 132 + 32 * 136) * 4;   // 84,992 B
    cudaFuncSetAttribute(proj_fused, cudaFuncAttributeMaxDynamicSharedMemorySize,
                         PROJ_SMEM);

    // Side stream for CSR build, forked/joined via events (graph-capturable).
    // Handles are intentionally leaked: destroying a stream/event that
    // participates in an active capture would invalidate the capture.
    cudaStream_t s_csr;
    cudaEvent_t ev_fork, ev_join;
    cudaStreamCreateWithFlags(&s_csr, cudaStreamNonBlocking);
    cudaEventCreateWithFlags(&ev_fork, cudaEventDisableTiming);
    cudaEventCreateWithFlags(&ev_join, cudaEventDisableTiming);

    // Main stream: dtype detect (needed by CSR too), then projection.
    detect_kernel<<<1, 1>>>((const unsigned long long*)ei);
    cudaEventRecord(ev_fork, 0);
    cudaStreamWaitEvent(s_csr, ev_fork, 0);

    // CSR build on side stream (overlaps with proj_fused below)
    k_zero<<<(NR + 255) / 256, 256, 0, s_csr>>>();
    k_hist<<<(NEDGE + 255) / 256, 256, 0, s_csr>>>(ei);
    k_scan1<<<SCAN_BLK, 1024, 0, s_csr>>>();
    k_scan2<<<1, 512, 0, s_csr>>>();
    k_scan3<<<SCAN_BLK, 1024, 0, s_csr>>>();
    k_scatter<<<(NEDGE + 255) / 256, 256, 0, s_csr>>>(ei);
    cudaEventRecord(ev_join, s_csr);

    // Projection on main stream
    proj_fused<<<(NN + 127) / 128, 256, PROJ_SMEM>>>(bond, W, b);

    // Join, then fused gather-reduce
    cudaStreamWaitEvent(0, ev_join, 0);
    edge_gather<<<dim3((NN + 7) / 8, NA), 256>>>(bond, out);
}

// round 11
// speedup vs baseline: 3.3430x; 1.1758x over previous
#include <cuda_runtime.h>
#include <cuda_fp16.h>
#include <math.h>
#include <string.h>

#define NN 100000   // nodes
#define NE 500000   // edges per head
#define NA 4        // angle heads
#define DD 128      // bond/hidden dim
#define NR (NA * NN)          // CSR rows (head-major)
#define NEDGE (NA * NE)       // total edges
#define SCAN_BLK 391          // ceil(NR / 1024)

// Scratch (allocation-guard-safe __device__ globals)
__device__ float   g_P1[(size_t)NA * NN * DD];    // dst-side projection + bias (fp32)
__device__ __half2 g_PX[(size_t)NA * NN * DD];    // (p2, x_j) fp16 pairs, src-side
__device__ int     g_is64;
__device__ int     g_count[NR];
__device__ int     g_offs[NR + 1];
__device__ int     g_cursor[NR];
__device__ int     g_bsum[512];
__device__ int     g_srcs[NEDGE];                 // dst-sorted src ids

// ---------------------------------------------------------------------------
// Bit-reinterpret helpers (nvcc lowers 4-byte reg-to-reg memcpy to a mov)
__device__ __forceinline__ unsigned h2_as_u(__half2 h) {
    unsigned u; memcpy(&u, &h, 4); return u;
}
__device__ __forceinline__ __half2 u_as_h2(unsigned u) {
    __half2 h; memcpy(&h, &u, 4); return h;
}

__global__ void detect_kernel(const unsigned long long* __restrict__ ei) {
    int ok = 1;
    for (int i = 0; i < 128; i++)
        if (ei[i] >= (unsigned long long)NN) { ok = 0; break; }
    g_is64 = ok;
}

__device__ __forceinline__ unsigned f2tf32(float v) {
    unsigned u;
    asm("cvt.rna.tf32.f32 %0, %1;" : "=r"(u) : "f"(v));
    return u;
}

__device__ __forceinline__ float tanh_fast(float x) {
    float y;
    asm("tanh.approx.f32 %0, %1;" : "=f"(y) : "f"(x));
    return y;
}

__device__ __forceinline__ void load_edge(const void* ei_raw, int a, int e,
                                          int& src, int& dst) {
    if (g_is64) {
        const long long* base = (const long long*)ei_raw + (size_t)a * 2 * NE;
        src = (int)__ldg(&base[e]);
        dst = (int)__ldg(&base[NE + e]);
    } else {
        const int* base = (const int*)ei_raw + (size_t)a * 2 * NE;
        src = __ldg(&base[e]);
        dst = __ldg(&base[NE + e]);
    }
}

// ---------------------------------------------------------------------------
// CSR build
// ---------------------------------------------------------------------------
__global__ void k_zero() {
    int i = blockIdx.x * blockDim.x + threadIdx.x;
    if (i < NR) g_count[i] = 0;
}

__global__ void k_hist(const void* __restrict__ ei_raw) {
    int i = blockIdx.x * blockDim.x + threadIdx.x;
    if (i >= NEDGE) return;
    int a = i / NE, e = i - a * NE;
    int src, dst;
    load_edge(ei_raw, a, e, src, dst);
    atomicAdd(&g_count[a * NN + dst], 1);
}

__global__ void __launch_bounds__(1024) k_scan1() {
    __shared__ int sh[1024];
    int t = threadIdx.x;
    int idx = blockIdx.x * 1024 + t;
    int v = (idx < NR) ? g_count[idx] : 0;
    sh[t] = v;
    __syncthreads();
#pragma unroll
    for (int d = 1; d < 1024; d <<= 1) {
        int x = (t >= d) ? sh[t - d] : 0;
        __syncthreads();
        sh[t] += x;
        __syncthreads();
    }
    if (idx < NR) g_offs[idx] = sh[t] - v;
    if (t == 1023) g_bsum[blockIdx.x] = sh[t];
}

__global__ void __launch_bounds__(512) k_scan2() {
    __shared__ int sh[512];
    int t = threadIdx.x;
    int v = (t < SCAN_BLK) ? g_bsum[t] : 0;
    sh[t] = v;
    __syncthreads();
#pragma unroll
    for (int d = 1; d < 512; d <<= 1) {
        int x = (t >= d) ? sh[t - d] : 0;
        __syncthreads();
        sh[t] += x;
        __syncthreads();
    }
    if (t < SCAN_BLK) g_bsum[t] = sh[t] - v;
}

__global__ void __launch_bounds__(1024) k_scan3() {
    int i = blockIdx.x * 1024 + threadIdx.x;
    if (i < NR) {
        int o = g_offs[i] + g_bsum[blockIdx.x];
        g_offs[i] = o;
        g_cursor[i] = o;
    }
    if (i == 0) g_offs[NR] = NEDGE;
}

__global__ void k_scatter(const void* __restrict__ ei_raw) {
    int i = blockIdx.x * blockDim.x + threadIdx.x;
    if (i >= NEDGE) return;
    int a = i / NE, e = i - a * NE;
    int src, dst;
    load_edge(ei_raw, a, e, src, dst);
    int pos = atomicAdd(&g_cursor[a * NN + dst], 1);
    g_srcs[pos] = src;
}

// ---------------------------------------------------------------------------
// Fused tf32 projection. half==0 -> g_P1 (fp32, +bias).
// half==1 -> g_PX as half2(p2, x_j) pairs (x_j read back from the As tile;
// As holds tf32-rounded bond values, exactly representable supersets of the
// mantissa fp16 keeps, so reading As vs bond is precision-equivalent here).
// ---------------------------------------------------------------------------
__global__ void __launch_bounds__(256)
proj_fused(const float* __restrict__ bond,
           const float* __restrict__ W,
           const float* __restrict__ bias) {
    extern __shared__ unsigned smem[];
    unsigned (*As)[132] = (unsigned (*)[132])smem;                // [128][132]
    unsigned (*Bs)[136] = (unsigned (*)[136])(smem + 128 * 132);  // [32][136]

    const int row0 = blockIdx.x * 128;
    const int tid  = threadIdx.x;
    const int lane = tid & 31;
    const int warp = tid >> 5;
    const int wm = warp & 3;
    const int wn = warp >> 2;
    const int g  = lane >> 2;
    const int tg = lane & 3;

#pragma unroll
    for (int i = 0; i < 16; i++) {
        int f = tid + i * 256;
        int r = f >> 5, c4 = f & 31;
        int grow = row0 + r;
        float4 v = make_float4(0.f, 0.f, 0.f, 0.f);
        if (grow < NN) v = *(const float4*)(bond + (size_t)grow * 128 + c4 * 4);
        uint4 u = make_uint4(f2tf32(v.x), f2tf32(v.y), f2tf32(v.z), f2tf32(v.w));
        *(uint4*)(&As[r][c4 * 4]) = u;
    }

    for (int combo = 0; combo < NA * 2; combo++) {
        const int head = combo >> 1;
        const int half = combo & 1;
        const float* Wbase = W + (size_t)(head * 256 + half * 128) * 128;

        float acc[2][8][4];
#pragma unroll
        for (int mt = 0; mt < 2; mt++)
#pragma unroll
            for (int nt = 0; nt < 8; nt++)
#pragma unroll
                for (int i = 0; i < 4; i++) acc[mt][nt][i] = 0.f;

        for (int kc = 0; kc < 4; kc++) {
            const int k0 = kc * 32;
            __syncthreads();
#pragma unroll
            for (int i = 0; i < 4; i++) {
                int f = tid + i * 256;
                int k = f >> 5, nq = f & 31;
                float4 v = *(const float4*)(Wbase + (size_t)(k0 + k) * 128 + nq * 4);
                Bs[k][nq * 4 + 0] = f2tf32(v.x);
                Bs[k][nq * 4 + 1] = f2tf32(v.y);
                Bs[k][nq * 4 + 2] = f2tf32(v.z);
                Bs[k][nq * 4 + 3] = f2tf32(v.w);
            }
            __syncthreads();

#pragma unroll
            for (int ks = 0; ks < 4; ks++) {
                const int kb = ks * 8;
                unsigned bfr[8][2], afr[2][4];
#pragma unroll
                for (int nt = 0; nt < 8; nt++) {
                    int n = wn * 64 + nt * 8 + g;
                    bfr[nt][0] = Bs[kb + tg][n];
                    bfr[nt][1] = Bs[kb + tg + 4][n];
                }
#pragma unroll
                for (int mt = 0; mt < 2; mt++) {
                    int m = wm * 32 + mt * 16 + g;
                    afr[mt][0] = As[m][k0 + kb + tg];
                    afr[mt][1] = As[m + 8][k0 + kb + tg];
                    afr[mt][2] = As[m][k0 + kb + tg + 4];
                    afr[mt][3] = As[m + 8][k0 + kb + tg + 4];
                }
#pragma unroll
                for (int mt = 0; mt < 2; mt++)
#pragma unroll
                    for (int nt = 0; nt < 8; nt++) {
                        asm volatile(
                            "mma.sync.aligned.m16n8k8.row.col.f32.tf32.tf32.f32 "
                            "{%0,%1,%2,%3}, {%4,%5,%6,%7}, {%8,%9}, {%0,%1,%2,%3};"
                            : "+f"(acc[mt][nt][0]), "+f"(acc[mt][nt][1]),
                              "+f"(acc[mt][nt][2]), "+f"(acc[mt][nt][3])
                            : "r"(afr[mt][0]), "r"(afr[mt][1]),
                              "r"(afr[mt][2]), "r"(afr[mt][3]),
                              "r"(bfr[nt][0]), "r"(bfr[nt][1]));
                    }
            }
        }

        const float* bv = bias + head * 128;
#pragma unroll
        for (int mt = 0; mt < 2; mt++) {
#pragma unroll
            for (int nt = 0; nt < 8; nt++) {
                int c   = wn * 64 + nt * 8 + 2 * tg;
                int rl0 = wm * 32 + mt * 16 + g;      // local rows
                int rl1 = rl0 + 8;
                int r0  = row0 + rl0;
                int r1  = row0 + rl1;
                if (!half) {
                    float b0 = bv[c], b1 = bv[c + 1];
                    if (r0 < NN) {
                        float2 v = make_float2(acc[mt][nt][0] + b0, acc[mt][nt][1] + b1);
                        *(float2*)(g_P1 + ((size_t)head * NN + r0) * 128 + c) = v;
                    }
                    if (r1 < NN) {
                        float2 v = make_float2(acc[mt][nt][2] + b0, acc[mt][nt][3] + b1);
                        *(float2*)(g_P1 + ((size_t)head * NN + r1) * 128 + c) = v;
                    }
                } else {
                    if (r0 < NN) {
                        float x0 = __uint_as_float(As[rl0][c]);
                        float x1 = __uint_as_float(As[rl0][c + 1]);
                        __half2 ha = __floats2half2_rn(acc[mt][nt][0], x0);  // (p2, xj)
                        __half2 hb = __floats2half2_rn(acc[mt][nt][1], x1);
                        uint2 wv = make_uint2(h2_as_u(ha), h2_as_u(hb));
                        *(uint2*)(g_PX + ((size_t)head * NN + r0) * 128 + c) = wv;
                    }
                    if (r1 < NN) {
                        float x0 = __uint_as_float(As[rl1][c]);
                        float x1 = __uint_as_float(As[rl1][c + 1]);
                        __half2 ha = __floats2half2_rn(acc[mt][nt][2], x0);
                        __half2 hb = __floats2half2_rn(acc[mt][nt][3], x1);
                        uint2 wv = make_uint2(h2_as_u(ha), h2_as_u(hb));
                        *(uint2*)(g_PX + ((size_t)head * NN + r1) * 128 + c) = wv;
                    }
                }
            }
        }
    }
}

// ---------------------------------------------------------------------------
// Gather-reduce: one warp per (node, head). Single 512B gather per edge.
// ---------------------------------------------------------------------------
__global__ void __launch_bounds__(256)
edge_gather(float* __restrict__ out) {
    const int a = blockIdx.y;
    const int node = blockIdx.x * 8 + (threadIdx.x >> 5);
    if (node >= NN) return;
    const int lane = threadIdx.x & 31;

    const int r = a * NN + node;
    const int e0 = __ldg(&g_offs[r]);
    const int e1 = __ldg(&g_offs[r + 1]);

    float4 acc = make_float4(0.f, 0.f, 0.f, 0.f);

    if (e0 < e1) {
        const float4 p1 = *(const float4*)(g_P1 + (size_t)r * 128 + lane * 4);
        const __half2* PXh = g_PX + (size_t)a * NN * 128;

        int e = e0;
        for (; e + 1 < e1; e += 2) {
            int s0 = __ldg(&g_srcs[e]);
            int s1 = __ldg(&g_srcs[e + 1]);
            uint4 ua = *(const uint4*)(PXh + (size_t)s0 * 128 + lane * 4);
            uint4 ub = *(const uint4*)(PXh + (size_t)s1 * 128 + lane * 4);
            float2 qa0 = __half22float2(u_as_h2(ua.x));
            float2 qa1 = __half22float2(u_as_h2(ua.y));
            float2 qa2 = __half22float2(u_as_h2(ua.z));
            float2 qa3 = __half22float2(u_as_h2(ua.w));
            float2 qb0 = __half22float2(u_as_h2(ub.x));
            float2 qb1 = __half22float2(u_as_h2(ub.y));
            float2 qb2 = __half22float2(u_as_h2(ub.z));
            float2 qb3 = __half22float2(u_as_h2(ub.w));
            acc.x += tanh_fast(p1.x + qa0.x) * qa0.y;
            acc.y += tanh_fast(p1.y + qa1.x) * qa1.y;
            acc.z += tanh_fast(p1.z + qa2.x) * qa2.y;
            acc.w += tanh_fast(p1.w + qa3.x) * qa3.y;
            acc.x += tanh_fast(p1.x + qb0.x) * qb0.y;
            acc.y += tanh_fast(p1.y + qb1.x) * qb1.y;
            acc.z += tanh_fast(p1.z + qb2.x) * qb2.y;
            acc.w += tanh_fast(p1.w + qb3.x) * qb3.y;
        }
        if (e < e1) {
            int s = __ldg(&g_srcs[e]);
            uint4 u = *(const uint4*)(PXh + (size_t)s * 128 + lane * 4);
            float2 q0 = __half22float2(u_as_h2(u.x));
            float2 q1 = __half22float2(u_as_h2(u.y));
            float2 q2 = __half22float2(u_as_h2(u.z));
            float2 q3 = __half22float2(u_as_h2(u.w));
            acc.x += tanh_fast(p1.x + q0.x) * q0.y;
            acc.y += tanh_fast(p1.y + q1.x) * q1.y;
            acc.z += tanh_fast(p1.z + q2.x) * q2.y;
            acc.w += tanh_fast(p1.w + q3.x) * q3.y;
        }
    }
    *(float4*)(out + (size_t)node * (NA * DD) + a * DD + lane * 4) = acc;
}

// ---------------------------------------------------------------------------
extern "C" void kernel_launch(void* const* d_in, const int* in_sizes, int n_in,
                              void* d_out, int out_size) {
    const float* bond = nullptr;
    const void*  ei   = nullptr;
    const float* W    = nullptr;
    const float* b    = nullptr;
    for (int i = 0; i < n_in; i++) {
        switch (in_sizes[i]) {
            case 12800000: bond = (const float*)d_in[i]; break;
            case 4000000:  ei   = d_in[i];               break;
            case 131072:   W    = (const float*)d_in[i]; break;
            case 512:      b    = (const float*)d_in[i]; break;
            default: break;
        }
    }
    float* out = (float*)d_out;   // [NN, NA*128] f32 — fully written by edge_gather

    const int PROJ_SMEM = (128 * 132 + 32 * 136) * 4;   // 84,992 B
    cudaFuncSetAttribute(proj_fused, cudaFuncAttributeMaxDynamicSharedMemorySize,
                         PROJ_SMEM);

    // Side stream for CSR build (graph-capturable fork/join; handles leaked
    // intentionally — destroying them mid-capture would invalidate capture).
    cudaStream_t s_csr;
    cudaEvent_t ev_fork, ev_join;
    cudaStreamCreateWithFlags(&s_csr, cudaStreamNonBlocking);
    cudaEventCreateWithFlags(&ev_fork, cudaEventDisableTiming);
    cudaEventCreateWithFlags(&ev_join, cudaEventDisableTiming);

    detect_kernel<<<1, 1>>>((const unsigned long long*)ei);
    cudaEventRecord(ev_fork, 0);
    cudaStreamWaitEvent(s_csr, ev_fork, 0);

    k_zero<<<(NR + 255) / 256, 256, 0, s_csr>>>();
    k_hist<<<(NEDGE + 255) / 256, 256, 0, s_csr>>>(ei);
    k_scan1<<<SCAN_BLK, 1024, 0, s_csr>>>();
    k_scan2<<<1, 512, 0, s_csr>>>();
    k_scan3<<<SCAN_BLK, 1024, 0, s_csr>>>();
    k_scatter<<<(NEDGE + 255) / 256, 256, 0, s_csr>>>(ei);
    cudaEventRecord(ev_join, s_csr);

    proj_fused<<<(NN + 127) / 128, 256, PROJ_SMEM>>>(bond, W, b);

    cudaStreamWaitEvent(0, ev_join, 0);
    edge_gather<<<dim3((NN + 7) / 8, NA), 256>>>(out);
}

// round 14
// speedup vs baseline: 3.6623x; 1.0955x over previous
#include <cuda_runtime.h>
#include <cuda_fp16.h>
#include <math.h>
#include <string.h>

#define NN 100000   // nodes
#define NE 500000   // edges per head
#define NA 4        // angle heads
#define DD 128      // bond/hidden dim
#define NR (NA * NN)          // CSR rows (head-major)
#define NEDGE (NA * NE)       // total edges
#define SCAN_BLK 391          // ceil(NR / 1024)

// Scratch (allocation-guard-safe __device__ globals)
__device__ __half2 g_P1h[(size_t)NA * NN * (DD / 2)];  // dst-side proj + bias (fp16 pairs)
__device__ __half2 g_PX[(size_t)NA * NN * DD];         // (p2, x_j) fp16 pairs, src-side
__device__ int     g_is64;
__device__ int     g_count[NR];
__device__ int     g_offs[NR + 1];
__device__ int     g_cursor[NR];
__device__ int     g_bsum[512];
__device__ int     g_srcs[NEDGE];                      // dst-sorted src ids

// ---------------------------------------------------------------------------
__device__ __forceinline__ unsigned h2_as_u(__half2 h) {
    unsigned u; memcpy(&u, &h, 4); return u;
}
__device__ __forceinline__ __half2 u_as_h2(unsigned u) {
    __half2 h; memcpy(&h, &u, 4); return h;
}

__global__ void detect_kernel(const unsigned long long* __restrict__ ei) {
    int ok = 1;
    for (int i = 0; i < 128; i++)
        if (ei[i] >= (unsigned long long)NN) { ok = 0; break; }
    g_is64 = ok;
}

__device__ __forceinline__ unsigned f2tf32(float v) {
    unsigned u;
    asm("cvt.rna.tf32.f32 %0, %1;" : "=r"(u) : "f"(v));
    return u;
}

__device__ __forceinline__ float tanh_fast(float x) {
    float y;
    asm("tanh.approx.f32 %0, %1;" : "=f"(y) : "f"(x));
    return y;
}

__device__ __forceinline__ void load_edge(const void* ei_raw, int a, int e,
                                          int& src, int& dst) {
    if (g_is64) {
        const long long* base = (const long long*)ei_raw + (size_t)a * 2 * NE;
        src = (int)__ldg(&base[e]);
        dst = (int)__ldg(&base[NE + e]);
    } else {
        const int* base = (const int*)ei_raw + (size_t)a * 2 * NE;
        src = __ldg(&base[e]);
        dst = __ldg(&base[NE + e]);
    }
}

// ---------------------------------------------------------------------------
// CSR build
// ---------------------------------------------------------------------------
__global__ void k_zero() {
    int i = blockIdx.x * blockDim.x + threadIdx.x;
    if (i < NR) g_count[i] = 0;
}

__global__ void k_hist(const void* __restrict__ ei_raw) {
    int i = blockIdx.x * blockDim.x + threadIdx.x;
    if (i >= NEDGE) return;
    int a = i / NE, e = i - a * NE;
    int src, dst;
    load_edge(ei_raw, a, e, src, dst);
    atomicAdd(&g_count[a * NN + dst], 1);
}

__global__ void __launch_bounds__(1024) k_scan1() {
    __shared__ int sh[1024];
    int t = threadIdx.x;
    int idx = blockIdx.x * 1024 + t;
    int v = (idx < NR) ? g_count[idx] : 0;
    sh[t] = v;
    __syncthreads();
#pragma unroll
    for (int d = 1; d < 1024; d <<= 1) {
        int x = (t >= d) ? sh[t - d] : 0;
        __syncthreads();
        sh[t] += x;
        __syncthreads();
    }
    if (idx < NR) g_offs[idx] = sh[t] - v;
    if (t == 1023) g_bsum[blockIdx.x] = sh[t];
}

__global__ void __launch_bounds__(512) k_scan2() {
    __shared__ int sh[512];
    int t = threadIdx.x;
    int v = (t < SCAN_BLK) ? g_bsum[t] : 0;
    sh[t] = v;
    __syncthreads();
#pragma unroll
    for (int d = 1; d < 512; d <<= 1) {
        int x = (t >= d) ? sh[t - d] : 0;
        __syncthreads();
        sh[t] += x;
        __syncthreads();
    }
    if (t < SCAN_BLK) g_bsum[t] = sh[t] - v;
}

__global__ void __launch_bounds__(1024) k_scan3() {
    int i = blockIdx.x * 1024 + threadIdx.x;
    if (i < NR) {
        int o = g_offs[i] + g_bsum[blockIdx.x];
        g_offs[i] = o;
        g_cursor[i] = o;
    }
    if (i == 0) g_offs[NR] = NEDGE;
}

__global__ void k_scatter(const void* __restrict__ ei_raw) {
    int i = blockIdx.x * blockDim.x + threadIdx.x;
    if (i >= NEDGE) return;
    int a = i / NE, e = i - a * NE;
    int src, dst;
    load_edge(ei_raw, a, e, src, dst);
    int pos = atomicAdd(&g_cursor[a * NN + dst], 1);
    g_srcs[pos] = src;
}

// ---------------------------------------------------------------------------
// Fused tf32 projection. half==0 -> g_P1h (fp16 pairs, +bias).
// half==1 -> g_PX as half2(p2, x_j) pairs (x_j read back from the As tile).
// ---------------------------------------------------------------------------
__global__ void __launch_bounds__(256)
proj_fused(const float* __restrict__ bond,
           const float* __restrict__ W,
           const float* __restrict__ bias) {
    extern __shared__ unsigned smem[];
    unsigned (*As)[132] = (unsigned (*)[132])smem;                // [128][132]
    unsigned (*Bs)[136] = (unsigned (*)[136])(smem + 128 * 132);  // [32][136]

    const int row0 = blockIdx.x * 128;
    const int tid  = threadIdx.x;
    const int lane = tid & 31;
    const int warp = tid >> 5;
    const int wm = warp & 3;
    const int wn = warp >> 2;
    const int g  = lane >> 2;
    const int tg = lane & 3;

#pragma unroll
    for (int i = 0; i < 16; i++) {
        int f = tid + i * 256;
        int r = f >> 5, c4 = f & 31;
        int grow = row0 + r;
        float4 v = make_float4(0.f, 0.f, 0.f, 0.f);
        if (grow < NN) v = *(const float4*)(bond + (size_t)grow * 128 + c4 * 4);
        uint4 u = make_uint4(f2tf32(v.x), f2tf32(v.y), f2tf32(v.z), f2tf32(v.w));
        *(uint4*)(&As[r][c4 * 4]) = u;
    }

    for (int combo = 0; combo < NA * 2; combo++) {
        const int head = combo >> 1;
        const int half = combo & 1;
        const float* Wbase = W + (size_t)(head * 256 + half * 128) * 128;

        float acc[2][8][4];
#pragma unroll
        for (int mt = 0; mt < 2; mt++)
#pragma unroll
            for (int nt = 0; nt < 8; nt++)
#pragma unroll
                for (int i = 0; i < 4; i++) acc[mt][nt][i] = 0.f;

        for (int kc = 0; kc < 4; kc++) {
            const int k0 = kc * 32;
            __syncthreads();
#pragma unroll
            for (int i = 0; i < 4; i++) {
                int f = tid + i * 256;
                int k = f >> 5, nq = f & 31;
                float4 v = *(const float4*)(Wbase + (size_t)(k0 + k) * 128 + nq * 4);
                Bs[k][nq * 4 + 0] = f2tf32(v.x);
                Bs[k][nq * 4 + 1] = f2tf32(v.y);
                Bs[k][nq * 4 + 2] = f2tf32(v.z);
                Bs[k][nq * 4 + 3] = f2tf32(v.w);
            }
            __syncthreads();

#pragma unroll
            for (int ks = 0; ks < 4; ks++) {
                const int kb = ks * 8;
                unsigned bfr[8][2], afr[2][4];
#pragma unroll
                for (int nt = 0; nt < 8; nt++) {
                    int n = wn * 64 + nt * 8 + g;
                    bfr[nt][0] = Bs[kb + tg][n];
                    bfr[nt][1] = Bs[kb + tg + 4][n];
                }
#pragma unroll
                for (int mt = 0; mt < 2; mt++) {
                    int m = wm * 32 + mt * 16 + g;
                    afr[mt][0] = As[m][k0 + kb + tg];
                    afr[mt][1] = As[m + 8][k0 + kb + tg];
                    afr[mt][2] = As[m][k0 + kb + tg + 4];
                    afr[mt][3] = As[m + 8][k0 + kb + tg + 4];
                }
#pragma unroll
                for (int mt = 0; mt < 2; mt++)
#pragma unroll
                    for (int nt = 0; nt < 8; nt++) {
                        asm volatile(
                            "mma.sync.aligned.m16n8k8.row.col.f32.tf32.tf32.f32 "
                            "{%0,%1,%2,%3}, {%4,%5,%6,%7}, {%8,%9}, {%0,%1,%2,%3};"
                            : "+f"(acc[mt][nt][0]), "+f"(acc[mt][nt][1]),
                              "+f"(acc[mt][nt][2]), "+f"(acc[mt][nt][3])
                            : "r"(afr[mt][0]), "r"(afr[mt][1]),
                              "r"(afr[mt][2]), "r"(afr[mt][3]),
                              "r"(bfr[nt][0]), "r"(bfr[nt][1]));
                    }
            }
        }

        const float* bv = bias + head * 128;
#pragma unroll
        for (int mt = 0; mt < 2; mt++) {
#pragma unroll
            for (int nt = 0; nt < 8; nt++) {
                int c   = wn * 64 + nt * 8 + 2 * tg;
                int rl0 = wm * 32 + mt * 16 + g;      // local rows
                int rl1 = rl0 + 8;
                int r0  = row0 + rl0;
                int r1  = row0 + rl1;
                if (!half) {
                    float b0 = bv[c], b1 = bv[c + 1];
                    if (r0 < NN) {
                        __half2 hv = __floats2half2_rn(acc[mt][nt][0] + b0,
                                                       acc[mt][nt][1] + b1);
                        g_P1h[((size_t)head * NN + r0) * 64 + (c >> 1)] = hv;
                    }
                    if (r1 < NN) {
                        __half2 hv = __floats2half2_rn(acc[mt][nt][2] + b0,
                                                       acc[mt][nt][3] + b1);
                        g_P1h[((size_t)head * NN + r1) * 64 + (c >> 1)] = hv;
                    }
                } else {
                    if (r0 < NN) {
                        float x0 = __uint_as_float(As[rl0][c]);
                        float x1 = __uint_as_float(As[rl0][c + 1]);
                        __half2 ha = __floats2half2_rn(acc[mt][nt][0], x0);  // (p2, xj)
                        __half2 hb = __floats2half2_rn(acc[mt][nt][1], x1);
                        uint2 wv = make_uint2(h2_as_u(ha), h2_as_u(hb));
                        *(uint2*)(g_PX + ((size_t)head * NN + r0) * 128 + c) = wv;
                    }
                    if (r1 < NN) {
                        float x0 = __uint_as_float(As[rl1][c]);
                        float x1 = __uint_as_float(As[rl1][c + 1]);
                        __half2 ha = __floats2half2_rn(acc[mt][nt][2], x0);
                        __half2 hb = __floats2half2_rn(acc[mt][nt][3], x1);
                        uint2 wv = make_uint2(h2_as_u(ha), h2_as_u(hb));
                        *(uint2*)(g_PX + ((size_t)head * NN + r1) * 128 + c) = wv;
                    }
                }
            }
        }
    }
}

// ---------------------------------------------------------------------------
// Gather-reduce: one warp per (node, head). 4/2/1 gather ladder; streaming
// cache hints on P1/out so the L2 stays reserved for PX gathers.
// ---------------------------------------------------------------------------
__device__ __forceinline__ void acc_one(float4& acc, const float4& p1, uint4 u) {
    float2 q0 = __half22float2(u_as_h2(u.x));
    float2 q1 = __half22float2(u_as_h2(u.y));
    float2 q2 = __half22float2(u_as_h2(u.z));
    float2 q3 = __half22float2(u_as_h2(u.w));
    acc.x += tanh_fast(p1.x + q0.x) * q0.y;
    acc.y += tanh_fast(p1.y + q1.x) * q1.y;
    acc.z += tanh_fast(p1.z + q2.x) * q2.y;
    acc.w += tanh_fast(p1.w + q3.x) * q3.y;
}

__global__ void __launch_bounds__(256)
edge_gather(float* __restrict__ out) {
    const int a = blockIdx.y;
    const int node = blockIdx.x * 8 + (threadIdx.x >> 5);
    if (node >= NN) return;
    const int lane = threadIdx.x & 31;

    const int r = a * NN + node;
    const int e0 = __ldg(&g_offs[r]);
    const int e1 = __ldg(&g_offs[r + 1]);

    float4 acc = make_float4(0.f, 0.f, 0.f, 0.f);

    if (e0 < e1) {
        // P1 row (fp16 pairs): streaming read, 8B/lane
        uint2 p1u = __ldcs((const uint2*)(g_P1h + (size_t)r * 64) + lane);
        float2 pa = __half22float2(u_as_h2(p1u.x));
        float2 pb = __half22float2(u_as_h2(p1u.y));
        const float4 p1 = make_float4(pa.x, pa.y, pb.x, pb.y);

        const __half2* PXh = g_PX + (size_t)a * NN * 128;

        int e = e0;
        for (; e + 3 < e1; e += 4) {
            int s0 = __ldg(&g_srcs[e]);
            int s1 = __ldg(&g_srcs[e + 1]);
            int s2 = __ldg(&g_srcs[e + 2]);
            int s3 = __ldg(&g_srcs[e + 3]);
            uint4 u0 = *(const uint4*)(PXh + (size_t)s0 * 128 + lane * 4);
            uint4 u1 = *(const uint4*)(PXh + (size_t)s1 * 128 + lane * 4);
            uint4 u2 = *(const uint4*)(PXh + (size_t)s2 * 128 + lane * 4);
            uint4 u3 = *(const uint4*)(PXh + (size_t)s3 * 128 + lane * 4);
            acc_one(acc, p1, u0);
            acc_one(acc, p1, u1);
            acc_one(acc, p1, u2);
            acc_one(acc, p1, u3);
        }
        if (e + 1 < e1) {
            int s0 = __ldg(&g_srcs[e]);
            int s1 = __ldg(&g_srcs[e + 1]);
            uint4 u0 = *(const uint4*)(PXh + (size_t)s0 * 128 + lane * 4);
            uint4 u1 = *(const uint4*)(PXh + (size_t)s1 * 128 + lane * 4);
            acc_one(acc, p1, u0);
            acc_one(acc, p1, u1);
            e += 2;
        }
        if (e < e1) {
            int s = __ldg(&g_srcs[e]);
            uint4 u = *(const uint4*)(PXh + (size_t)s * 128 + lane * 4);
            acc_one(acc, p1, u);
        }
    }
    // Streaming store: don't let 205MB of output evict PX from L2
    __stcs((float4*)(out + (size_t)node * (NA * DD) + a * DD) + lane, acc);
}

// ---------------------------------------------------------------------------
extern "C" void kernel_launch(void* const* d_in, const int* in_sizes, int n_in,
                              void* d_out, int out_size) {
    const float* bond = nullptr;
    const void*  ei   = nullptr;
    const float* W    = nullptr;
    const float* b    = nullptr;
    for (int i = 0; i < n_in; i++) {
        switch (in_sizes[i]) {
            case 12800000: bond = (const float*)d_in[i]; break;
            case 4000000:  ei   = d_in[i];               break;
            case 131072:   W    = (const float*)d_in[i]; break;
            case 512:      b    = (const float*)d_in[i]; break;
            default: break;
        }
    }
    float* out = (float*)d_out;   // [NN, NA*128] f32 — fully written by edge_gather

    const int PROJ_SMEM = (128 * 132 + 32 * 136) * 4;   // 84,992 B
    cudaFuncSetAttribute(proj_fused, cudaFuncAttributeMaxDynamicSharedMemorySize,
                         PROJ_SMEM);

    // Side stream for detect + CSR build (graph-capturable fork/join; handles
    // leaked intentionally — destroying mid-capture would invalidate capture).
    cudaStream_t s_csr;
    cudaEvent_t ev_fork, ev_join;
    cudaStreamCreateWithFlags(&s_csr, cudaStreamNonBlocking);
    cudaEventCreateWithFlags(&ev_fork, cudaEventDisableTiming);
    cudaEventCreateWithFlags(&ev_join, cudaEventDisableTiming);

    cudaEventRecord(ev_fork, 0);
    cudaStreamWaitEvent(s_csr, ev_fork, 0);

    // CSR chain (detect gates only this chain, so it lives here too)
    detect_kernel<<<1, 1, 0, s_csr>>>((const unsigned long long*)ei);
    k_zero<<<(NR + 255) / 256, 256, 0, s_csr>>>();
    k_hist<<<(NEDGE + 255) / 256, 256, 0, s_csr>>>(ei);
    k_scan1<<<SCAN_BLK, 1024, 0, s_csr>>>();
    k_scan2<<<1, 512, 0, s_csr>>>();
    k_scan3<<<SCAN_BLK, 1024, 0, s_csr>>>();
    k_scatter<<<(NEDGE + 255) / 256, 256, 0, s_csr>>>(ei);
    cudaEventRecord(ev_join, s_csr);

    // Projection starts immediately on main stream
    proj_fused<<<(NN + 127) / 128, 256, PROJ_SMEM>>>(bond, W, b);

    cudaStreamWaitEvent(0, ev_join, 0);
    edge_gather<<<dim3((NN + 7) / 8, NA), 256>>>(out);
}